// round 3
// baseline (speedup 1.0000x reference)
#include <cuda_runtime.h>

#define Hh 51
#define NB 4
#define NTH 416                          // 13 warps
#define BTOT 512
#define ROWF 112                         // [0..50]=h1, [51]=x, [52..102]=h2, [103..111]=0
#define BUF_BYTES (NB * ROWF * 4)        // 1792 B per double-buffer half

__device__ __forceinline__ unsigned long long pack2(float lo, float hi) {
    unsigned long long r;
    asm("mov.b64 %0, {%1,%2};" : "=l"(r) : "f"(lo), "f"(hi));
    return r;
}
__device__ __forceinline__ void ffma2(unsigned long long &acc, unsigned long long a, unsigned long long b) {
    asm("fma.rn.f32x2 %0, %1, %2, %0;" : "+l"(acc) : "l"(a), "l"(b));
}
__device__ __forceinline__ float sum2(unsigned long long a) {
    float lo, hi;
    asm("mov.b64 {%0,%1}, %2;" : "=f"(lo), "=f"(hi) : "l"(a));
    return lo + hi;
}
__device__ __forceinline__ void lds128(unsigned long long &p0, unsigned long long &p1, unsigned addr) {
    asm volatile("ld.shared.v2.b64 {%0,%1}, [%2];" : "=l"(p0), "=l"(p1) : "r"(addr));
}
__device__ __forceinline__ float fsig(float x) {
    return __fdividef(1.f, 1.f + __expf(-x));
}
__device__ __forceinline__ float ftanh_(float x) {
    float ax = fabsf(x);
    float e  = __expf(2.f * ax);
    float r  = 1.f - __fdividef(2.f, e + 1.f);
    return (x < 0.f) ? -r : r;
}

// 4x4 transpose across lane bits 2..3 (gate <-> batch-slot).
__device__ __forceinline__ void transp4(float v[4], int lane) {
    {
        bool lo = lane & 4;
        float tA = lo ? v[0] : v[1];
        float tB = lo ? v[2] : v[3];
        tA = __shfl_xor_sync(0xffffffffu, tA, 4);
        tB = __shfl_xor_sync(0xffffffffu, tB, 4);
        if (lo) { v[0] = tA; v[2] = tB; } else { v[1] = tA; v[3] = tB; }
    }
    {
        bool hi = lane & 8;
        float uA = hi ? v[0] : v[2];
        float uB = hi ? v[1] : v[3];
        uA = __shfl_xor_sync(0xffffffffu, uA, 8);
        uB = __shfl_xor_sync(0xffffffffu, uB, 8);
        if (hi) { v[0] = uA; v[1] = uB; } else { v[2] = uA; v[3] = uB; }
    }
}

__global__ void __launch_bounds__(NTH, 1)
lstm2_kernel(const float* __restrict__ input,
             const float* __restrict__ W_ih1, const float* __restrict__ W_hh1,
             const float* __restrict__ b_ih1, const float* __restrict__ b_hh1,
             const float* __restrict__ W_ih2, const float* __restrict__ W_hh2,
             const float* __restrict__ b_ih2, const float* __restrict__ b_hh2,
             const float* __restrict__ W_lin, const float* __restrict__ b_lin,
             float* __restrict__ out, int T, int Ttot)
{
    __shared__ __align__(16) float hcat[2][NB][ROWF];
    __shared__ __align__(16) float pbuf[NB][68];

    const int  tid  = threadIdx.x;
    const int  lane = tid & 31;
    const int  wid  = tid >> 5;
    const int  j2   = lane & 3;                 // j within warp
    const int  q    = (lane >> 2) & 3;          // gate for dots; batch for update
    const int  kh   = lane >> 4;                // K-half
    const int  j    = wid * 4 + j2;
    const bool act  = (j < Hh);
    const int  b0   = blockIdx.x * NB;
    const int  row  = q * Hh + (act ? j : 0);

    const bool pre_lane = (wid == 12) && (j2 == 3) && (kh == 0);  // x prefetch, batch q
    const bool red_lane = (wid == 12) && (j2 == 3) && (kh == 1);  // out reduce, batch q

    for (int i = tid; i < 2 * NB * ROWF; i += NTH) (&hcat[0][0][0])[i] = 0.f;
    if (tid < NB) hcat[1][tid][51] = input[(b0 + tid) * T];       // x(0) -> prev of t=0

    // ---- per-lane K-half weights (packed pairs) ----
    // layer1 vector L1[f]: f<51 -> W_hh1[row][f]; f==51 -> W_ih1[row]; else 0
    // layer2 lo  L2lo[f]: f<51 -> W_ih2[row][f]; else 0          (f in 0..55)
    // layer2 hi  L2hi[f]: f<51 -> W_hh2[row][f]; else 0          (local f in 0..55)
    unsigned long long w1[14], w2lo[14], w2hi[14];
    {
        const float* r1 = W_hh1 + row * Hh;
        const float* ri = W_ih2 + row * Hh;
        const float* rh = W_hh2 + row * Hh;
        const int pb = kh * 14;
        #pragma unroll
        for (int i = 0; i < 14; ++i) {
            const int f0 = 2 * (pb + i), f1 = f0 + 1;
            float a0 = 0.f, a1v = 0.f, l0 = 0.f, l1v = 0.f, h0 = 0.f, h1v = 0.f;
            if (act) {
                a0  = (f0 < 51) ? r1[f0] : ((f0 == 51) ? W_ih1[row] : 0.f);
                a1v = (f1 < 51) ? r1[f1] : ((f1 == 51) ? W_ih1[row] : 0.f);
                l0  = (f0 < 51) ? ri[f0] : 0.f;
                l1v = (f1 < 51) ? ri[f1] : 0.f;
                h0  = (f0 < 51) ? rh[f0] : 0.f;
                h1v = (f1 < 51) ? rh[f1] : 0.f;
            }
            w1[i]   = pack2(a0, a1v);
            w2lo[i] = pack2(l0, l1v);
            w2hi[i] = pack2(h0, h1v);
        }
    }
    const float bs1  = (act && kh == 0) ? (b_ih1[row] + b_hh1[row]) : 0.f;
    const float bs2  = (act && kh == 0) ? (b_ih2[row] + b_hh2[row]) : 0.f;
    const float wl   = act ? W_lin[j] : 0.f;
    const float blin = b_lin[0];

    unsigned hb[NB];
    #pragma unroll
    for (int b = 0; b < NB; ++b)
        hb[b] = (unsigned)__cvta_generic_to_shared(&hcat[0][b][0]);

    const unsigned off_lo0 = (unsigned)(kh * 7) * 16u;          // chunks 0..13
    const unsigned off_hi0 = (unsigned)(13 + kh * 7) * 16u;     // chunks 13..26

    float c1 = 0.f, c2 = 0.f, xpre = 0.f;
    __syncthreads();

    for (int t = 0; t < Ttot; ++t) {
        const unsigned co = (t & 1) ? (unsigned)BUF_BYTES : 0u;
        const unsigned po = co ^ (unsigned)BUF_BYTES;

        // ---- spare duties (pad lanes of warp 12), overlapped with phase A ----
        if (pre_lane && (t + 1 < T))
            xpre = input[(b0 + q) * T + (t + 1)];
        if (red_lane && t >= 1 && t < T) {               // deferred output for t-1
            float4 s4 = make_float4(0.f, 0.f, 0.f, 0.f);
            const float4* p4 = (const float4*)&pbuf[q][0];
            #pragma unroll
            for (int k = 0; k < 12; ++k) {
                float4 v4 = p4[k];
                s4.x += v4.x; s4.y += v4.y; s4.z += v4.z; s4.w += v4.w;
            }
            float s = (s4.x + s4.y) + (s4.z + s4.w)
                    + pbuf[q][48] + pbuf[q][49] + pbuf[q][50] + blin;
            out[(b0 + q) * Ttot + (t - 1)] = s;
        }

        // ---- phase A: layer-1 dot (prev, chunks 0..13) + layer-2 h2-half (prev, 13..26) ----
        unsigned long long a1[NB], a2[NB];
        #pragma unroll
        for (int b = 0; b < NB; ++b) { a1[b] = pack2(bs1, 0.f); a2[b] = pack2(bs2, 0.f); }
        #pragma unroll
        for (int i = 0; i < 7; ++i) {
            #pragma unroll
            for (int b = 0; b < NB; ++b) {
                unsigned long long p0, p1, q0, q1;
                lds128(p0, p1, hb[b] + po + off_lo0 + i * 16u);
                lds128(q0, q1, hb[b] + po + off_hi0 + i * 16u);
                ffma2(a1[b], w1[2*i],       p0);
                ffma2(a1[b], w1[2*i + 1],   p1);
                ffma2(a2[b], w2hi[2*i],     q0);
                ffma2(a2[b], w2hi[2*i + 1], q1);
            }
        }
        float v[4];
        #pragma unroll
        for (int b = 0; b < NB; ++b) {
            float s = sum2(a1[b]);
            s += __shfl_xor_sync(0xffffffffu, s, 16);    // K-half reduce
            v[b] = s;
        }
        transp4(v, lane);                                // v=[i,f,g,o] for (batch q, j)
        {
            float cg = fsig(v[1]) * c1 + fsig(v[0]) * ftanh_(v[2]);
            c1 = cg;
            float h1 = fsig(v[3]) * ftanh_(cg);
            if (act && kh == 0) hcat[t & 1][q][j] = h1;
        }
        __syncthreads();                                 // B_A

        // ---- phase B: layer-2 h1-half dot (cur, chunks 0..13; x slot weight 0) ----
        if (pre_lane && (t + 1 < T)) hcat[t & 1][q][51] = xpre;
        #pragma unroll
        for (int i = 0; i < 7; ++i) {
            #pragma unroll
            for (int b = 0; b < NB; ++b) {
                unsigned long long p0, p1;
                lds128(p0, p1, hb[b] + co + off_lo0 + i * 16u);
                ffma2(a2[b], w2lo[2*i],     p0);
                ffma2(a2[b], w2lo[2*i + 1], p1);
            }
        }
        #pragma unroll
        for (int b = 0; b < NB; ++b) {
            float s = sum2(a2[b]);
            s += __shfl_xor_sync(0xffffffffu, s, 16);
            v[b] = s;
        }
        transp4(v, lane);
        {
            float cg = fsig(v[1]) * c2 + fsig(v[0]) * ftanh_(v[2]);
            c2 = cg;
            float h2v = fsig(v[3]) * ftanh_(cg);
            if (act && kh == 0) {
                hcat[t & 1][q][52 + j] = h2v;
                pbuf[q][j] = wl * h2v;
            }
        }
        __syncthreads();                                 // B_B

        // ---- autoregressive tail: out(t) feeds x(t+1) ----
        if (t >= T - 1) {
            if (red_lane) {
                float4 s4 = make_float4(0.f, 0.f, 0.f, 0.f);
                const float4* p4 = (const float4*)&pbuf[q][0];
                #pragma unroll
                for (int k = 0; k < 12; ++k) {
                    float4 v4 = p4[k];
                    s4.x += v4.x; s4.y += v4.y; s4.z += v4.z; s4.w += v4.w;
                }
                float s = (s4.x + s4.y) + (s4.z + s4.w)
                        + pbuf[q][48] + pbuf[q][49] + pbuf[q][50] + blin;
                out[(b0 + q) * Ttot + t] = s;
                hcat[t & 1][q][51] = s;                  // x(t+1)
            }
            __syncthreads();                             // B_C (AR only)
        }
    }
}

extern "C" void kernel_launch(void* const* d_in, const int* in_sizes, int n_in,
                              void* d_out, int out_size) {
    const float* input = (const float*)d_in[0];
    const float* W_ih1 = (const float*)d_in[1];
    const float* W_hh1 = (const float*)d_in[2];
    const float* b_ih1 = (const float*)d_in[3];
    const float* b_hh1 = (const float*)d_in[4];
    const float* W_ih2 = (const float*)d_in[5];
    const float* W_hh2 = (const float*)d_in[6];
    const float* b_ih2 = (const float*)d_in[7];
    const float* b_hh2 = (const float*)d_in[8];
    const float* W_lin = (const float*)d_in[9];
    const float* b_lin = (const float*)d_in[10];

    const int T    = in_sizes[0] / BTOT;   // 1024
    const int Ttot = out_size    / BTOT;   // 1088

    lstm2_kernel<<<BTOT / NB, NTH>>>(input, W_ih1, W_hh1, b_ih1, b_hh1,
                                     W_ih2, W_hh2, b_ih2, b_hh2,
                                     W_lin, b_lin,
                                     (float*)d_out, T, Ttot);
}

// round 6
// speedup vs baseline: 1.4085x; 1.4085x over previous
#include <cuda_runtime.h>

#define Hh 51
#define NB 4
#define NTH 224
#define BTOT 512
#define ROWF 104                        // [0..50]=h1, [51]=x, [52..102]=h2, [103]=0
#define BUF_BYTES (NB * ROWF * 4)       // bytes per double-buffer half

__device__ __forceinline__ unsigned long long pack2(float lo, float hi) {
    unsigned long long r;
    asm("mov.b64 %0, {%1,%2};" : "=l"(r) : "f"(lo), "f"(hi));
    return r;
}
__device__ __forceinline__ void ffma2(unsigned long long &acc, unsigned long long a, unsigned long long b) {
    asm("fma.rn.f32x2 %0, %1, %2, %0;" : "+l"(acc) : "l"(a), "l"(b));
}
__device__ __forceinline__ float sum2(unsigned long long a) {
    float lo, hi;
    asm("mov.b64 {%0,%1}, %2;" : "=f"(lo), "=f"(hi) : "l"(a));
    return lo + hi;
}
__device__ __forceinline__ void lds128(unsigned long long &p0, unsigned long long &p1, unsigned addr) {
    asm volatile("ld.shared.v2.b64 {%0,%1}, [%2];" : "=l"(p0), "=l"(p1) : "r"(addr));
}
__device__ __forceinline__ float fsig(float x) {
    return __fdividef(1.f, 1.f + __expf(-x));
}
__device__ __forceinline__ float ftanh_(float x) {
    float ax = fabsf(x);
    float e  = __expf(2.f * ax);
    float r  = 1.f - __fdividef(2.f, e + 1.f);
    return (x < 0.f) ? -r : r;
}

// 4x4 transpose across lane bits 3..4 (gate <-> batch-slot).
__device__ __forceinline__ void transp4(float v[4], int lane) {
    {
        bool lo = lane & 8;
        float tA = lo ? v[0] : v[1];
        float tB = lo ? v[2] : v[3];
        tA = __shfl_xor_sync(0xffffffffu, tA, 8);
        tB = __shfl_xor_sync(0xffffffffu, tB, 8);
        if (lo) { v[0] = tA; v[2] = tB; } else { v[1] = tA; v[3] = tB; }
    }
    {
        bool hi = lane & 16;
        float uA = hi ? v[0] : v[2];
        float uB = hi ? v[1] : v[3];
        uA = __shfl_xor_sync(0xffffffffu, uA, 16);
        uB = __shfl_xor_sync(0xffffffffu, uB, 16);
        if (hi) { v[0] = uA; v[1] = uB; } else { v[2] = uA; v[3] = uB; }
    }
}

__global__ void __launch_bounds__(NTH, 1)
lstm2_kernel(const float* __restrict__ input,
             const float* __restrict__ W_ih1, const float* __restrict__ W_hh1,
             const float* __restrict__ b_ih1, const float* __restrict__ b_hh1,
             const float* __restrict__ W_ih2, const float* __restrict__ W_hh2,
             const float* __restrict__ b_ih2, const float* __restrict__ b_hh2,
             const float* __restrict__ W_lin, const float* __restrict__ b_lin,
             float* __restrict__ out, int T, int Ttot)
{
    __shared__ __align__(16) float hcat[2][NB][ROWF];   // double-buffered (R2 scheme)
    __shared__ __align__(16) float pbuf[NB][68];

    const int  tid  = threadIdx.x;
    const int  lane = tid & 31;
    const int  wid  = tid >> 5;
    const int  jloc = lane & 7;
    const int  q    = (lane >> 3) & 3;          // gate index for dots; batch index for update
    const int  j    = wid * 8 + jloc;
    const bool act  = (j < Hh);
    const int  b0   = blockIdx.x * NB;
    const int  row  = q * Hh + (act ? j : 0);

    const bool pre_lane = (wid == 6) && (jloc == 3);    // x(t+1) prefetch, batch q
    const bool red_lane = (wid == 6) && (jloc == 4);    // output reduction, batch q

    for (int i = tid; i < 2 * NB * ROWF; i += NTH) (&hcat[0][0][0])[i] = 0.f;
    __syncthreads();                                    // order init before x(0) store
    if (tid < NB) hcat[1][tid][51] = input[(b0 + tid) * T];   // x(0) into prev-buffer of t=0

    // ---- weights, packed along K into 64-bit pairs (registers) ----
    // w1n : layer-1 recurrent over slots 0..51 (slot 51 -> 0; x handled via wi1 scalar)
    // w2p : layer-2 over slots 0..103 (0..50 = W_ih2 on h1, 51 -> 0, 52..102 = W_hh2 on h2, 103 -> 0)
    unsigned long long w1n[26], w2p[52];
    {
        const float* r1 = W_hh1 + row * Hh;
        #pragma unroll
        for (int k = 0; k < 26; ++k) {
            int k0 = 2*k, k1 = 2*k + 1;
            float a = (act && k0 < 51) ? r1[k0] : 0.f;
            float b = (act && k1 < 51) ? r1[k1] : 0.f;
            w1n[k] = pack2(a, b);
        }
        const float* ri = W_ih2 + row * Hh;   // multiplies h1
        const float* rh = W_hh2 + row * Hh;   // multiplies h2
        #pragma unroll
        for (int k = 0; k < 52; ++k) {
            int k0 = 2*k, k1 = 2*k + 1;
            float a = 0.f, b = 0.f;
            if (act) {
                a = (k0 < 51) ? ri[k0] : ((k0 >= 52 && k0 <= 102) ? rh[k0 - 52] : 0.f);
                b = (k1 < 51) ? ri[k1] : ((k1 >= 52 && k1 <= 102) ? rh[k1 - 52] : 0.f);
            }
            w2p[k] = pack2(a, b);
        }
    }
    const float wi1  = act ? W_ih1[row] : 0.f;
    const float bs1  = act ? (b_ih1[row] + b_hh1[row]) : 0.f;
    const float bs2  = act ? (b_ih2[row] + b_hh2[row]) : 0.f;
    const float wl   = act ? W_lin[j] : 0.f;
    const float blin = b_lin[0];

    unsigned hb[NB];
    #pragma unroll
    for (int b = 0; b < NB; ++b)
        hb[b] = (unsigned)__cvta_generic_to_shared(&hcat[0][b][0]);

    float c1 = 0.f, c2 = 0.f, xpre = 0.f;
    unsigned long long a1n[NB];
    #pragma unroll
    for (int b = 0; b < NB; ++b) a1n[b] = pack2(bs1, 0.f);   // layer-1 gates for t=0 (W_hh1·0)

    __syncthreads();

    for (int t = 0; t < Ttot; ++t) {
        const unsigned co = (t & 1) ? (unsigned)BUF_BYTES : 0u;   // cur buffer
        const unsigned po = co ^ (unsigned)BUF_BYTES;             // prev buffer
        const int      pi = (t & 1) ^ 1;                          // prev buffer index

        // ---- spare duties (warp 6), overlapped with phase A ----
        if (pre_lane && (t + 1 < T))
            xpre = input[(b0 + q) * T + (t + 1)];
        if (red_lane && t >= 1 && t < T) {       // deferred output for step t-1
            float4 s4 = make_float4(0.f, 0.f, 0.f, 0.f);
            const float4* p4 = (const float4*)&pbuf[q][0];
            #pragma unroll
            for (int k = 0; k < 12; ++k) {
                float4 v4 = p4[k];
                s4.x += v4.x; s4.y += v4.y; s4.z += v4.z; s4.w += v4.w;
            }
            float s = (s4.x + s4.y) + (s4.z + s4.w)
                    + pbuf[q][48] + pbuf[q][49] + pbuf[q][50] + blin;
            out[(b0 + q) * Ttot + (t - 1)] = s;
        }

        // ---- phase A: layer-2 h2-half dot (prev floats 52..103)
        //               + layer-1 update from carried a1n + x(t) ----
        unsigned long long a2[NB];
        #pragma unroll
        for (int b = 0; b < NB; ++b) a2[b] = pack2(bs2, 0.f);
        #pragma unroll
        for (int kk = 0; kk < 13; ++kk) {
            #pragma unroll
            for (int b = 0; b < NB; ++b) {
                unsigned long long q0, q1;
                lds128(q0, q1, hb[b] + po + 208 + kk * 16);
                ffma2(a2[b], w2p[26 + 2*kk], q0);
                ffma2(a2[b], w2p[27 + 2*kk], q1);
            }
        }
        float v[4];
        #pragma unroll
        for (int b = 0; b < NB; ++b)
            v[b] = fmaf(hcat[pi][b][51], wi1, sum2(a1n[b]));   // x(t) from prev slot 51
        transp4(v, lane);                         // v = [i,f,g,o] for (batch q, row j)
        {
            float cg = fsig(v[1]) * c1 + fsig(v[0]) * ftanh_(v[2]);
            c1 = cg;
            float h1 = fsig(v[3]) * ftanh_(cg);
            if (act) hcat[t & 1][q][j] = h1;      // new h1 -> cur buffer
        }
        __syncthreads();                          // B_A

        // ---- phase B: joint dot over cur floats 0..51 (h1(t); slot 51 weight 0)
        //               a2 += W_ih2·h1 ; a1n' = bs1 + W_hh1·h1 ----
        if (pre_lane && (t + 1 < T)) hcat[t & 1][q][51] = xpre;   // x(t+1) -> cur buffer
        #pragma unroll
        for (int b = 0; b < NB; ++b) a1n[b] = pack2(bs1, 0.f);
        #pragma unroll
        for (int kk = 0; kk < 13; ++kk) {
            #pragma unroll
            for (int b = 0; b < NB; ++b) {
                unsigned long long p0, p1;
                lds128(p0, p1, hb[b] + co + kk * 16);
                ffma2(a2[b],  w2p[2*kk],     p0);
                ffma2(a2[b],  w2p[2*kk + 1], p1);
                ffma2(a1n[b], w1n[2*kk],     p0);
                ffma2(a1n[b], w1n[2*kk + 1], p1);
            }
        }
        #pragma unroll
        for (int b = 0; b < NB; ++b) v[b] = sum2(a2[b]);
        transp4(v, lane);
        {
            float cg = fsig(v[1]) * c2 + fsig(v[0]) * ftanh_(v[2]);
            c2 = cg;
            float h2v = fsig(v[3]) * ftanh_(cg);
            if (act) {
                hcat[t & 1][q][52 + j] = h2v;     // new h2 -> cur buffer
                pbuf[q][j] = wl * h2v;
            }
        }
        __syncthreads();                          // B_B

        // ---- autoregressive tail: out(t) feeds x(t+1) ----
        if (t >= T - 1) {
            if (red_lane) {
                float4 s4 = make_float4(0.f, 0.f, 0.f, 0.f);
                const float4* p4 = (const float4*)&pbuf[q][0];
                #pragma unroll
                for (int k = 0; k < 12; ++k) {
                    float4 v4 = p4[k];
                    s4.x += v4.x; s4.y += v4.y; s4.z += v4.z; s4.w += v4.w;
                }
                float s = (s4.x + s4.y) + (s4.z + s4.w)
                        + pbuf[q][48] + pbuf[q][49] + pbuf[q][50] + blin;
                out[(b0 + q) * Ttot + t] = s;
                hcat[t & 1][q][51] = s;           // x(t+1) into cur (= prev of t+1)
            }
            __syncthreads();                      // B_C (AR region only)
        }
    }
}

extern "C" void kernel_launch(void* const* d_in, const int* in_sizes, int n_in,
                              void* d_out, int out_size) {
    const float* input = (const float*)d_in[0];
    const float* W_ih1 = (const float*)d_in[1];
    const float* W_hh1 = (const float*)d_in[2];
    const float* b_ih1 = (const float*)d_in[3];
    const float* b_hh1 = (const float*)d_in[4];
    const float* W_ih2 = (const float*)d_in[5];
    const float* W_hh2 = (const float*)d_in[6];
    const float* b_ih2 = (const float*)d_in[7];
    const float* b_hh2 = (const float*)d_in[8];
    const float* W_lin = (const float*)d_in[9];
    const float* b_lin = (const float*)d_in[10];

    const int T    = in_sizes[0] / BTOT;   // 1024
    const int Ttot = out_size    / BTOT;   // 1088

    lstm2_kernel<<<BTOT / NB, NTH>>>(input, W_ih1, W_hh1, b_ih1, b_hh1,
                                     W_ih2, W_hh2, b_ih2, b_hh2,
                                     W_lin, b_lin,
                                     (float*)d_out, T, Ttot);
}